// round 13
// baseline (speedup 1.0000x reference)
#include <cuda_runtime.h>
#include <cstdint>

#define NB     16
#define NROWS  128
#define NT     128
#define NVOCAB 258
typedef unsigned long long u64;

// ---------------- static device scratch ----------------
__device__ __align__(16) float  g_proj[NVOCAB * 96];
__device__ __align__(16) float4 g_w4[3 * 2 * 3 * 8 * 32];    // [l][side][gate][chunk][j]
__device__ __align__(16) float  g_cbias[96];
__device__ __align__(16) float  g_w64[96];
__device__ __align__(16) float  g_wvt[32 * NVOCAB];          // w_out^T [k][v]
__device__ __align__(16) float  g_hout[NROWS * NT * 16 * 32]; // [rt][b][j]
__device__ int g_flag[NROWS];

// ---------------- helpers ----------------
__device__ __forceinline__ int ld_acq(const int* p) {
    int v; asm volatile("ld.acquire.gpu.s32 %0, [%1];" : "=r"(v) : "l"(p) : "memory"); return v;
}
__device__ __forceinline__ void st_rel(int* p, int v) {
    asm volatile("st.release.gpu.s32 [%0], %1;" :: "l"(p), "r"(v) : "memory");
}
__device__ __forceinline__ u64 dup2(float x) {
    u64 r; unsigned xi = __float_as_uint(x);
    asm("mov.b64 %0, {%1, %1};" : "=l"(r) : "r"(xi)); return r;
}
__device__ __forceinline__ u64 pack2(float a, float b) {
    u64 r; asm("mov.b64 %0, {%1, %2};" : "=l"(r) : "r"(__float_as_uint(a)), "r"(__float_as_uint(b)));
    return r;
}
__device__ __forceinline__ float2 unpk(u64 v) {
    unsigned lo, hi; asm("mov.b64 {%0, %1}, %2;" : "=r"(lo), "=r"(hi) : "l"(v));
    return make_float2(__uint_as_float(lo), __uint_as_float(hi));
}
__device__ __forceinline__ u64 fma2(u64 a, u64 b, u64 c) {
    u64 d; asm("fma.rn.f32x2 %0, %1, %2, %3;" : "=l"(d) : "l"(a), "l"(b), "l"(c)); return d;
}
__device__ __forceinline__ float tanh_ap(float x) {
    float y; asm("tanh.approx.f32 %0, %1;" : "=f"(y) : "f"(x)); return y;
}
__device__ __forceinline__ float sig_ap(float x) { return fmaf(tanh_ap(x * 0.5f), 0.5f, 0.5f); }

// ---------------- prep ----------------
__global__ void prep_kernel(
    const float* __restrict__ embed,
    const float* __restrict__ wih0, const float* __restrict__ whh0,
    const float* __restrict__ wih1, const float* __restrict__ whh1,
    const float* __restrict__ wih2, const float* __restrict__ whh2,
    const float* __restrict__ w_h2e, const float* __restrict__ b_h2e,
    const float* __restrict__ bih0, const float* __restrict__ w_out)
{
    const int v = blockIdx.x;
    const int g = threadIdx.x;       // 0..95
    if (v < NVOCAB) {
        float s = 0.0f;
        #pragma unroll 8
        for (int e = 0; e < 64; ++e) s = fmaf(embed[v * 64 + e], wih0[g * 65 + e], s);
        g_proj[v * 96 + g] = s;
    } else if (v == NVOCAB) {
        const int gate = g >> 5, j = g & 31;
        float cb = bih0[g];
        for (int e = 0; e < 65; ++e) cb = fmaf(wih0[g * 65 + e], b_h2e[e], cb);
        g_cbias[g] = cb;
        g_w64[g] = wih0[g * 65 + 64];
        float wc[32];
        #pragma unroll
        for (int k = 0; k < 32; ++k) {
            float s = 0.0f;
            for (int e = 0; e < 65; ++e) s = fmaf(wih0[g * 65 + e], w_h2e[e * 32 + k], s);
            wc[k] = s;
        }
        const float* Wm[3][2] = {{0, whh0}, {wih1, whh1}, {wih2, whh2}};
        #pragma unroll
        for (int c = 0; c < 8; ++c) {
            g_w4[(((0 * 2 + 0) * 3 + gate) * 8 + c) * 32 + j] =
                make_float4(wc[4*c], wc[4*c+1], wc[4*c+2], wc[4*c+3]);
            for (int l = 0; l < 3; ++l)
                for (int s_ = 0; s_ < 2; ++s_) {
                    const float* W = Wm[l][s_];
                    if (!W) continue;
                    g_w4[(((l * 2 + s_) * 3 + gate) * 8 + c) * 32 + j] =
                        make_float4(W[g*32+4*c], W[g*32+4*c+1], W[g*32+4*c+2], W[g*32+4*c+3]);
                }
        }
    } else {
        for (int i = g; i < 32 * NVOCAB; i += 96) {
            int k = i / NVOCAB, vv = i % NVOCAB;
            g_wvt[i] = w_out[vv * 32 + k];
        }
    }
}

__global__ void reset_kernel() {
    int i = threadIdx.x;
    if (i < NROWS) g_flag[i] = 0;
}

__global__ void noop_kernel() {}   // pad launch position so rnn lands at slot 4 for ncu

// ---------------- one GRU layer from smem; k-pair f32x2, 2 batches/thread ----------------
__device__ __forceinline__ void layer_step(
    const float* __restrict__ wsl,            // layer base (6144 floats)
    const float* __restrict__ insm,           // [2][8][36]
    const float* __restrict__ hq,             // [2][8][36]
    float* __restrict__ hp,                   // [2][8][36]
    int j, int bp,
    float cr, float cz, float cn, float ch,
    float ar0, float ar1, float az0, float az1, float an0, float an1,
    float* __restrict__ hold)
{
    const ulonglong2* wir = (const ulonglong2*)(wsl)        + j;
    const ulonglong2* wiz = (const ulonglong2*)(wsl + 1024) + j;
    const ulonglong2* win = (const ulonglong2*)(wsl + 2048) + j;
    const ulonglong2* whr = (const ulonglong2*)(wsl + 3072) + j;
    const ulonglong2* whz = (const ulonglong2*)(wsl + 4096) + j;
    const ulonglong2* whn = (const ulonglong2*)(wsl + 5120) + j;
    u64 ar[2] = { pack2(cr + ar0, 0.f), pack2(cr + ar1, 0.f) };
    u64 az[2] = { pack2(cz + az0, 0.f), pack2(cz + az1, 0.f) };
    u64 ai[2] = { pack2(cn + an0, 0.f), pack2(cn + an1, 0.f) };
    u64 ah[2] = { pack2(ch, 0.f),       pack2(ch, 0.f) };
    const int row0 = bp * 36;              // bi=0 half
    const int row1 = (8 + bp) * 36;        // bi=1 half
    #pragma unroll
    for (int c = 0; c < 8; ++c) {
        ulonglong2 w_ir = wir[c * 32];
        ulonglong2 w_iz = wiz[c * 32];
        ulonglong2 w_in = win[c * 32];
        ulonglong2 w_hr = whr[c * 32];
        ulonglong2 w_hz = whz[c * 32];
        ulonglong2 w_hn = whn[c * 32];
        #pragma unroll
        for (int bi = 0; bi < 2; ++bi) {
            const int ro = bi ? row1 : row0;
            ulonglong2 xv = *(const ulonglong2*)&insm[ro + 4 * c];
            ulonglong2 hv = *(const ulonglong2*)&hq[ro + 4 * c];
            ar[bi] = fma2(w_ir.x, xv.x, ar[bi]); ar[bi] = fma2(w_ir.y, xv.y, ar[bi]);
            ar[bi] = fma2(w_hr.x, hv.x, ar[bi]); ar[bi] = fma2(w_hr.y, hv.y, ar[bi]);
            az[bi] = fma2(w_iz.x, xv.x, az[bi]); az[bi] = fma2(w_iz.y, xv.y, az[bi]);
            az[bi] = fma2(w_hz.x, hv.x, az[bi]); az[bi] = fma2(w_hz.y, hv.y, az[bi]);
            ai[bi] = fma2(w_in.x, xv.x, ai[bi]); ai[bi] = fma2(w_in.y, xv.y, ai[bi]);
            ah[bi] = fma2(w_hn.x, hv.x, ah[bi]); ah[bi] = fma2(w_hn.y, hv.y, ah[bi]);
        }
    }
    #pragma unroll
    for (int bi = 0; bi < 2; ++bi) {
        float2 fr = unpk(ar[bi]), fz = unpk(az[bi]);
        float2 fi = unpk(ai[bi]), fh = unpk(ah[bi]);
        float rr = sig_ap(fr.x + fr.y), zz = sig_ap(fz.x + fz.y);
        float nn = tanh_ap(fmaf(rr, fh.x + fh.y, fi.x + fi.y));
        float hv = fmaf(zz, hold[bi] - nn, nn);
        hold[bi] = hv;
        hp[(bi ? row1 : row0) + j] = hv;
    }
}

// ---------------- persistent wavefront: CTA=row (16 batches, 256 thr) ----------------
// dyn smem (bytes): ws 73728 | proj_s 103200 | prevsh 2304 | hbuf 13824 | toksh 8256
#define SMEM_RNN 201312
__global__ __launch_bounds__(256) void rnn_kernel(
    const int* __restrict__ x,
    const float* __restrict__ bhh0,
    const float* __restrict__ bih1, const float* __restrict__ bhh1,
    const float* __restrict__ bih2, const float* __restrict__ bhh2)
{
    extern __shared__ __align__(16) char smem[];
    float* ws     = (float*)smem;                        // 18432 floats
    float* proj_s = (float*)(smem + 73728);              // [258][100]
    float* prevsh = (float*)(smem + 73728 + 103200);     // [2][8][36]
    float* hbuf   = (float*)(smem + 73728 + 103200 + 2304);   // [6][2][8][36]
    int*   toksh  = (int*)  (smem + 73728 + 103200 + 2304 + 13824); // [16][129]

    const int tid = threadIdx.x;
    const int j   = tid >> 3;        // unit 0..31
    const int bp  = tid & 7;         // batch pair 0..7 (batches 2bp, 2bp+1)
    const int r   = blockIdx.x;

    // prologue: copy weights + proj + tokens to smem; zero buffers
    for (int idx = tid; idx < 4608; idx += 256)
        ((float4*)ws)[idx] = ((const float4*)g_w4)[idx];
    for (int idx = tid; idx < NVOCAB * 96; idx += 256) {
        int v = idx / 96, g = idx - v * 96;
        proj_s[v * 100 + g] = g_proj[idx];
    }
    for (int idx = tid; idx < 16 * 128; idx += 256) {
        int b = idx >> 7, tt = idx & 127;
        toksh[b * 129 + tt] = x[b * (NROWS * NT) + r * NT + tt];
    }
    for (int idx = tid; idx < 576; idx += 256) prevsh[idx] = 0.f;
    for (int idx = tid; idx < 6 * 576; idx += 256) hbuf[idx] = 0.f;

    const float rf = (float)r * (2.f / 128.f) - 1.f;
    const float c_r0 = fmaf(rf, g_w64[j],      g_cbias[j])      + bhh0[j];
    const float c_z0 = fmaf(rf, g_w64[32 + j], g_cbias[32 + j]) + bhh0[32 + j];
    const float c_n0 = fmaf(rf, g_w64[64 + j], g_cbias[64 + j]);
    const float c_h0 = bhh0[64 + j];
    const float c_r1 = bih1[j] + bhh1[j];
    const float c_z1 = bih1[32 + j] + bhh1[32 + j];
    const float c_n1 = bih1[64 + j];
    const float c_h1 = bhh1[64 + j];
    const float c_r2 = bih2[j] + bhh2[j];
    const float c_z2 = bih2[32 + j] + bhh2[32 + j];
    const float c_n2 = bih2[64 + j];
    const float c_h2 = bhh2[64 + j];

    float h0old[2] = {0.f, 0.f}, h1old[2] = {0.f, 0.f}, h2old[2] = {0.f, 0.f};

    int*       myflag   = &g_flag[r];
    const int* prevflag = &g_flag[r - 1];
    __syncthreads();

    for (int t = 0; t < NT; ++t) {
        const int p = t & 1, q = p ^ 1;
        const int tk0 = toksh[(2 * bp) * 129 + t];
        const int tk1 = toksh[(2 * bp + 1) * 129 + t];
        const float pr0 = proj_s[tk0 * 100 + j];
        const float pz0 = proj_s[tk0 * 100 + 32 + j];
        const float pn0 = proj_s[tk0 * 100 + 64 + j];
        const float pr1 = proj_s[tk1 * 100 + j];
        const float pz1 = proj_s[tk1 * 100 + 32 + j];
        const float pn1 = proj_s[tk1 * 100 + 64 + j];

        if (r > 0) {
            while (ld_acq(prevflag) < t + 1) { }
            if (tid < 128) {
                // float4 tid covers batch b = tid>>3, units 4q..4q+3 (q = tid&7)
                float4 pv = __ldcg(&((const float4*)g_hout)[((r - 1) * NT + t) * 128 + tid]);
                int b = tid >> 3, qq = tid & 7;
                *(float4*)&prevsh[((b & 1) * 8 + (b >> 1)) * 36 + 4 * qq] = pv;
            }
        }
        __syncthreads();                                       // bar A

        layer_step(ws,         prevsh,            hbuf + (0 * 2 + q) * 576, hbuf + (0 * 2 + p) * 576,
                   j, bp, c_r0, c_z0, c_n0, c_h0, pr0, pr1, pz0, pz1, pn0, pn1, h0old);
        __syncthreads();                                       // bar B
        layer_step(ws + 6144,  hbuf + (0 * 2 + p) * 576, hbuf + (1 * 2 + q) * 576, hbuf + (1 * 2 + p) * 576,
                   j, bp, c_r1, c_z1, c_n1, c_h1, 0.f, 0.f, 0.f, 0.f, 0.f, 0.f, h1old);
        __syncthreads();                                       // bar C
        layer_step(ws + 12288, hbuf + (1 * 2 + p) * 576, hbuf + (2 * 2 + q) * 576, hbuf + (2 * 2 + p) * 576,
                   j, bp, c_r2, c_z2, c_n2, c_h2, 0.f, 0.f, 0.f, 0.f, 0.f, 0.f, h2old);

        __stcg(&g_hout[(r * NT + t) * 512 + (2 * bp + 0) * 32 + j], h2old[0]);
        __stcg(&g_hout[(r * NT + t) * 512 + (2 * bp + 1) * 32 + j], h2old[1]);
        __syncthreads();                                       // bar D
        if (tid == 0) st_rel(myflag, t + 1);
    }
}

// ---------------- epilogue: block = (half, 4 rt-cells), thread = vocab scalar ----------------
__global__ __launch_bounds__(256) void out_kernel(
    float* __restrict__ outp, const float* __restrict__ b_out)
{
    __shared__ __align__(16) u64 hp[32][16];   // [k][cp]; cp = rt_i*4 + bpair
    const int tid  = threadIdx.x;
    const int half = blockIdx.x & 1;
    const int rt0  = (blockIdx.x >> 1) * 4;

    {
        int rt_i = tid >> 6, rem = tid & 63;
        float4 hv = __ldcg(&((const float4*)g_hout)[(rt0 + rt_i) * 128 +
                                                    (half * 8 + (rem >> 3)) * 8 + (rem & 7)]);
        int b = rem >> 3, kq = (rem & 7) * 4;
        int cp = rt_i * 4 + (b >> 1), hf = b & 1;
        ((float*)&hp[kq + 0][cp])[hf] = hv.x;
        ((float*)&hp[kq + 1][cp])[hf] = hv.y;
        ((float*)&hp[kq + 2][cp])[hf] = hv.z;
        ((float*)&hp[kq + 3][cp])[hf] = hv.w;
    }
    __syncthreads();

    for (int v = tid; v < NVOCAB; v += 256) {
        u64 acc[16];
        const u64 bia = dup2(__ldg(&b_out[v]));
        #pragma unroll
        for (int cp = 0; cp < 16; ++cp) acc[cp] = bia;
        #pragma unroll
        for (int k = 0; k < 32; ++k) {
            const u64 wv = dup2(__ldg(&g_wvt[k * NVOCAB + v]));
            const ulonglong2* hk = (const ulonglong2*)hp[k];
            #pragma unroll
            for (int qq = 0; qq < 8; ++qq) {
                ulonglong2 h2 = hk[qq];
                acc[2 * qq + 0] = fma2(wv, h2.x, acc[2 * qq + 0]);
                acc[2 * qq + 1] = fma2(wv, h2.y, acc[2 * qq + 1]);
            }
        }
        #pragma unroll
        for (int cp = 0; cp < 16; ++cp) {
            int rt_i = cp >> 2, bpp = cp & 3;
            long rt = rt0 + rt_i;
            long bb0 = half * 8 + 2 * bpp;
            float2 o = unpk(acc[cp]);
            outp[(bb0 * (NROWS * NT) + rt) * NVOCAB + v] = o.x;
            outp[((bb0 + 1) * (NROWS * NT) + rt) * NVOCAB + v] = o.y;
        }
    }
}

// ---------------- launch: positions (1 prep, 2 reset, 3 noop, 4 rnn, 5 out) ----------------
extern "C" void kernel_launch(void* const* d_in, const int* in_sizes, int n_in,
                              void* d_out, int out_size)
{
    (void)in_sizes; (void)n_in; (void)out_size;
    const int*   x     = (const int*)  d_in[0];
    const float* embed = (const float*)d_in[1];
    const float* wih0  = (const float*)d_in[2];
    const float* whh0  = (const float*)d_in[3];
    const float* bih0  = (const float*)d_in[4];
    const float* bhh0  = (const float*)d_in[5];
    const float* wih1  = (const float*)d_in[6];
    const float* whh1  = (const float*)d_in[7];
    const float* bih1  = (const float*)d_in[8];
    const float* bhh1  = (const float*)d_in[9];
    const float* wih2  = (const float*)d_in[10];
    const float* whh2  = (const float*)d_in[11];
    const float* bih2  = (const float*)d_in[12];
    const float* bhh2  = (const float*)d_in[13];
    const float* w_h2e = (const float*)d_in[14];
    const float* b_h2e = (const float*)d_in[15];
    const float* w_out = (const float*)d_in[16];
    const float* b_out = (const float*)d_in[17];
    float* outp = (float*)d_out;

    cudaFuncSetAttribute(rnn_kernel, cudaFuncAttributeMaxDynamicSharedMemorySize, SMEM_RNN);

    prep_kernel<<<260, 96>>>(embed, wih0, whh0, wih1, whh1, wih2, whh2,
                             w_h2e, b_h2e, bih0, w_out);
    reset_kernel<<<1, 128>>>();
    noop_kernel<<<1, 32>>>();
    rnn_kernel<<<NROWS, 256, SMEM_RNN>>>(x, bhh0, bih1, bhh1, bih2, bhh2);
    out_kernel<<<(NROWS * NT / 4) * 2, 256>>>(outp, b_out);
}

// round 14
// speedup vs baseline: 1.1100x; 1.1100x over previous
#include <cuda_runtime.h>
#include <cstdint>

#define NB     16
#define NROWS  128
#define NT     128
#define NVOCAB 258
typedef unsigned long long u64;

// ---------------- static device scratch ----------------
__device__ __align__(16) float  g_proj[NVOCAB * 96];
__device__ __align__(16) float4 g_w4[3 * 2 * 3 * 8 * 32];    // [l][side][gate][chunk][j]
__device__ __align__(16) float  g_cbias[96];
__device__ __align__(16) float  g_w64[96];
__device__ __align__(16) float  g_wvt[32 * NVOCAB];          // w_out^T [k][v]
__device__ __align__(16) float  g_hout[NROWS * NT * 16 * 32]; // [rt][b][j]
__device__ int g_flag[NROWS];

// ---------------- helpers ----------------
__device__ __forceinline__ int ld_rlx(const int* p) {
    int v; asm volatile("ld.relaxed.gpu.global.s32 %0, [%1];" : "=r"(v) : "l"(p) : "memory"); return v;
}
__device__ __forceinline__ void fence_acq() {
    asm volatile("fence.acq_rel.gpu;" ::: "memory");
}
__device__ __forceinline__ void st_rel(int* p, int v) {
    asm volatile("st.release.gpu.s32 [%0], %1;" :: "l"(p), "r"(v) : "memory");
}
__device__ __forceinline__ u64 dup2(float x) {
    u64 r; unsigned xi = __float_as_uint(x);
    asm("mov.b64 %0, {%1, %1};" : "=l"(r) : "r"(xi)); return r;
}
__device__ __forceinline__ u64 pack2(float a, float b) {
    u64 r; asm("mov.b64 %0, {%1, %2};" : "=l"(r) : "r"(__float_as_uint(a)), "r"(__float_as_uint(b)));
    return r;
}
__device__ __forceinline__ float2 unpk(u64 v) {
    unsigned lo, hi; asm("mov.b64 {%0, %1}, %2;" : "=r"(lo), "=r"(hi) : "l"(v));
    return make_float2(__uint_as_float(lo), __uint_as_float(hi));
}
__device__ __forceinline__ u64 fma2(u64 a, u64 b, u64 c) {
    u64 d; asm("fma.rn.f32x2 %0, %1, %2, %3;" : "=l"(d) : "l"(a), "l"(b), "l"(c)); return d;
}
__device__ __forceinline__ float tanh_ap(float x) {
    float y; asm("tanh.approx.f32 %0, %1;" : "=f"(y) : "f"(x)); return y;
}
__device__ __forceinline__ float sig_ap(float x) { return fmaf(tanh_ap(x * 0.5f), 0.5f, 0.5f); }

// ---------------- prep ----------------
__global__ void prep_kernel(
    const float* __restrict__ embed,
    const float* __restrict__ wih0, const float* __restrict__ whh0,
    const float* __restrict__ wih1, const float* __restrict__ whh1,
    const float* __restrict__ wih2, const float* __restrict__ whh2,
    const float* __restrict__ w_h2e, const float* __restrict__ b_h2e,
    const float* __restrict__ bih0, const float* __restrict__ w_out)
{
    const int v = blockIdx.x;
    const int g = threadIdx.x;       // 0..95
    if (v < NVOCAB) {
        float s = 0.0f;
        #pragma unroll 8
        for (int e = 0; e < 64; ++e) s = fmaf(embed[v * 64 + e], wih0[g * 65 + e], s);
        g_proj[v * 96 + g] = s;
    } else if (v == NVOCAB) {
        const int gate = g >> 5, j = g & 31;
        float cb = bih0[g];
        for (int e = 0; e < 65; ++e) cb = fmaf(wih0[g * 65 + e], b_h2e[e], cb);
        g_cbias[g] = cb;
        g_w64[g] = wih0[g * 65 + 64];
        float wc[32];
        #pragma unroll
        for (int k = 0; k < 32; ++k) {
            float s = 0.0f;
            for (int e = 0; e < 65; ++e) s = fmaf(wih0[g * 65 + e], w_h2e[e * 32 + k], s);
            wc[k] = s;
        }
        const float* Wm[3][2] = {{0, whh0}, {wih1, whh1}, {wih2, whh2}};
        #pragma unroll
        for (int c = 0; c < 8; ++c) {
            g_w4[(((0 * 2 + 0) * 3 + gate) * 8 + c) * 32 + j] =
                make_float4(wc[4*c], wc[4*c+1], wc[4*c+2], wc[4*c+3]);
            for (int l = 0; l < 3; ++l)
                for (int s_ = 0; s_ < 2; ++s_) {
                    const float* W = Wm[l][s_];
                    if (!W) continue;
                    g_w4[(((l * 2 + s_) * 3 + gate) * 8 + c) * 32 + j] =
                        make_float4(W[g*32+4*c], W[g*32+4*c+1], W[g*32+4*c+2], W[g*32+4*c+3]);
                }
        }
    } else {
        for (int i = g; i < 32 * NVOCAB; i += 96) {
            int k = i / NVOCAB, vv = i % NVOCAB;
            g_wvt[i] = w_out[vv * 32 + k];
        }
    }
}

__global__ void reset_kernel() {
    int i = threadIdx.x;
    if (i < NROWS) g_flag[i] = 0;
}

__global__ void noop_kernel() {}   // pad launch position so rnn lands at slot 4 for ncu

// ---------------- one GRU layer from smem; k-pair f32x2, 2 batches/thread ----------------
__device__ __forceinline__ void layer_step(
    const float* __restrict__ wsl,            // layer base (6144 floats)
    const float* __restrict__ insm,           // [2][8][36]
    const float* __restrict__ hq,             // [2][8][36]
    float* __restrict__ hp,                   // [2][8][36]
    int j, int bp,
    float cr, float cz, float cn, float ch,
    float ar0, float ar1, float az0, float az1, float an0, float an1,
    float* __restrict__ hold)
{
    const ulonglong2* wir = (const ulonglong2*)(wsl)        + j;
    const ulonglong2* wiz = (const ulonglong2*)(wsl + 1024) + j;
    const ulonglong2* win = (const ulonglong2*)(wsl + 2048) + j;
    const ulonglong2* whr = (const ulonglong2*)(wsl + 3072) + j;
    const ulonglong2* whz = (const ulonglong2*)(wsl + 4096) + j;
    const ulonglong2* whn = (const ulonglong2*)(wsl + 5120) + j;
    u64 ar[2] = { pack2(cr + ar0, 0.f), pack2(cr + ar1, 0.f) };
    u64 az[2] = { pack2(cz + az0, 0.f), pack2(cz + az1, 0.f) };
    u64 ai[2] = { pack2(cn + an0, 0.f), pack2(cn + an1, 0.f) };
    u64 ah[2] = { pack2(ch, 0.f),       pack2(ch, 0.f) };
    const int row0 = bp * 36;              // bi=0 half
    const int row1 = (8 + bp) * 36;        // bi=1 half
    #pragma unroll
    for (int c = 0; c < 8; ++c) {
        ulonglong2 w_ir = wir[c * 32];
        ulonglong2 w_iz = wiz[c * 32];
        ulonglong2 w_in = win[c * 32];
        ulonglong2 w_hr = whr[c * 32];
        ulonglong2 w_hz = whz[c * 32];
        ulonglong2 w_hn = whn[c * 32];
        #pragma unroll
        for (int bi = 0; bi < 2; ++bi) {
            const int ro = bi ? row1 : row0;
            ulonglong2 xv = *(const ulonglong2*)&insm[ro + 4 * c];
            ulonglong2 hv = *(const ulonglong2*)&hq[ro + 4 * c];
            ar[bi] = fma2(w_ir.x, xv.x, ar[bi]); ar[bi] = fma2(w_ir.y, xv.y, ar[bi]);
            ar[bi] = fma2(w_hr.x, hv.x, ar[bi]); ar[bi] = fma2(w_hr.y, hv.y, ar[bi]);
            az[bi] = fma2(w_iz.x, xv.x, az[bi]); az[bi] = fma2(w_iz.y, xv.y, az[bi]);
            az[bi] = fma2(w_hz.x, hv.x, az[bi]); az[bi] = fma2(w_hz.y, hv.y, az[bi]);
            ai[bi] = fma2(w_in.x, xv.x, ai[bi]); ai[bi] = fma2(w_in.y, xv.y, ai[bi]);
            ah[bi] = fma2(w_hn.x, hv.x, ah[bi]); ah[bi] = fma2(w_hn.y, hv.y, ah[bi]);
        }
    }
    #pragma unroll
    for (int bi = 0; bi < 2; ++bi) {
        float2 fr = unpk(ar[bi]), fz = unpk(az[bi]);
        float2 fi = unpk(ai[bi]), fh = unpk(ah[bi]);
        float rr = sig_ap(fr.x + fr.y), zz = sig_ap(fz.x + fz.y);
        float nn = tanh_ap(fmaf(rr, fh.x + fh.y, fi.x + fi.y));
        float hv = fmaf(zz, hold[bi] - nn, nn);
        hold[bi] = hv;
        hp[(bi ? row1 : row0) + j] = hv;
    }
}

// ---------------- persistent wavefront: CTA=row (16 batches, 256 thr) ----------------
// dyn smem (bytes): ws 73728 | proj_s 103200 | prevsh 2304 | hbuf 13824 | toksh 8256
#define SMEM_RNN 201312
__global__ __launch_bounds__(256) void rnn_kernel(
    const int* __restrict__ x,
    const float* __restrict__ bhh0,
    const float* __restrict__ bih1, const float* __restrict__ bhh1,
    const float* __restrict__ bih2, const float* __restrict__ bhh2)
{
    extern __shared__ __align__(16) char smem[];
    float* ws     = (float*)smem;                        // 18432 floats
    float* proj_s = (float*)(smem + 73728);              // [258][100]
    float* prevsh = (float*)(smem + 73728 + 103200);     // [2][8][36]
    float* hbuf   = (float*)(smem + 73728 + 103200 + 2304);   // [6][2][8][36]
    int*   toksh  = (int*)  (smem + 73728 + 103200 + 2304 + 13824); // [16][129]

    const int tid = threadIdx.x;
    const int j   = tid >> 3;        // unit 0..31
    const int bp  = tid & 7;         // batch pair 0..7 (batches 2bp, 2bp+1)
    const int r   = blockIdx.x;

    // prologue: copy weights + proj + tokens to smem; zero buffers
    for (int idx = tid; idx < 4608; idx += 256)
        ((float4*)ws)[idx] = ((const float4*)g_w4)[idx];
    for (int idx = tid; idx < NVOCAB * 96; idx += 256) {
        int v = idx / 96, g = idx - v * 96;
        proj_s[v * 100 + g] = g_proj[idx];
    }
    for (int idx = tid; idx < 16 * 128; idx += 256) {
        int b = idx >> 7, tt = idx & 127;
        toksh[b * 129 + tt] = x[b * (NROWS * NT) + r * NT + tt];
    }
    for (int idx = tid; idx < 576; idx += 256) prevsh[idx] = 0.f;
    for (int idx = tid; idx < 6 * 576; idx += 256) hbuf[idx] = 0.f;

    const float rf = (float)r * (2.f / 128.f) - 1.f;
    const float c_r0 = fmaf(rf, g_w64[j],      g_cbias[j])      + bhh0[j];
    const float c_z0 = fmaf(rf, g_w64[32 + j], g_cbias[32 + j]) + bhh0[32 + j];
    const float c_n0 = fmaf(rf, g_w64[64 + j], g_cbias[64 + j]);
    const float c_h0 = bhh0[64 + j];
    const float c_r1 = bih1[j] + bhh1[j];
    const float c_z1 = bih1[32 + j] + bhh1[32 + j];
    const float c_n1 = bih1[64 + j];
    const float c_h1 = bhh1[64 + j];
    const float c_r2 = bih2[j] + bhh2[j];
    const float c_z2 = bih2[32 + j] + bhh2[32 + j];
    const float c_n2 = bih2[64 + j];
    const float c_h2 = bhh2[64 + j];

    float h0old[2] = {0.f, 0.f}, h1old[2] = {0.f, 0.f}, h2old[2] = {0.f, 0.f};

    int*       myflag   = &g_flag[r];
    const int* prevflag = &g_flag[r - 1];
    __syncthreads();

    for (int t = 0; t < NT; ++t) {
        const int p = t & 1, q = p ^ 1;
        const int tk0 = toksh[(2 * bp) * 129 + t];
        const int tk1 = toksh[(2 * bp + 1) * 129 + t];
        const float pr0 = proj_s[tk0 * 100 + j];
        const float pz0 = proj_s[tk0 * 100 + 32 + j];
        const float pn0 = proj_s[tk0 * 100 + 64 + j];
        const float pr1 = proj_s[tk1 * 100 + j];
        const float pz1 = proj_s[tk1 * 100 + 32 + j];
        const float pn1 = proj_s[tk1 * 100 + 64 + j];

        if (r > 0) {
            // leader-spin: relaxed poll (no per-iteration L1 invalidation),
            // ONE acquire fence on success, barrier propagates ordering to CTA.
            if (tid == 0) {
                while (ld_rlx(prevflag) < t + 1) { }
                fence_acq();
            }
            __syncthreads();                                   // bar A1: flag seen
            if (tid < 128) {
                float4 pv = __ldcg(&((const float4*)g_hout)[((r - 1) * NT + t) * 128 + tid]);
                int b = tid >> 3, qq = tid & 7;
                *(float4*)&prevsh[((b & 1) * 8 + (b >> 1)) * 36 + 4 * qq] = pv;
            }
        }
        __syncthreads();                                       // bar A2: prevsh ready

        layer_step(ws,         prevsh,            hbuf + (0 * 2 + q) * 576, hbuf + (0 * 2 + p) * 576,
                   j, bp, c_r0, c_z0, c_n0, c_h0, pr0, pr1, pz0, pz1, pn0, pn1, h0old);
        __syncthreads();                                       // bar B
        layer_step(ws + 6144,  hbuf + (0 * 2 + p) * 576, hbuf + (1 * 2 + q) * 576, hbuf + (1 * 2 + p) * 576,
                   j, bp, c_r1, c_z1, c_n1, c_h1, 0.f, 0.f, 0.f, 0.f, 0.f, 0.f, h1old);
        __syncthreads();                                       // bar C
        layer_step(ws + 12288, hbuf + (1 * 2 + p) * 576, hbuf + (2 * 2 + q) * 576, hbuf + (2 * 2 + p) * 576,
                   j, bp, c_r2, c_z2, c_n2, c_h2, 0.f, 0.f, 0.f, 0.f, 0.f, 0.f, h2old);

        __stcg(&g_hout[(r * NT + t) * 512 + (2 * bp + 0) * 32 + j], h2old[0]);
        __stcg(&g_hout[(r * NT + t) * 512 + (2 * bp + 1) * 32 + j], h2old[1]);
        __syncthreads();                                       // bar D
        if (tid == 0) st_rel(myflag, t + 1);
    }
}

// ---------------- epilogue: block = (half, 4 rt-cells), thread = vocab scalar ----------------
__global__ __launch_bounds__(256) void out_kernel(
    float* __restrict__ outp, const float* __restrict__ b_out)
{
    __shared__ __align__(16) u64 hp[32][16];   // [k][cp]; cp = rt_i*4 + bpair
    const int tid  = threadIdx.x;
    const int half = blockIdx.x & 1;
    const int rt0  = (blockIdx.x >> 1) * 4;

    {
        int rt_i = tid >> 6, rem = tid & 63;
        float4 hv = __ldcg(&((const float4*)g_hout)[(rt0 + rt_i) * 128 +
                                                    (half * 8 + (rem >> 3)) * 8 + (rem & 7)]);
        int b = rem >> 3, kq = (rem & 7) * 4;
        int cp = rt_i * 4 + (b >> 1), hf = b & 1;
        ((float*)&hp[kq + 0][cp])[hf] = hv.x;
        ((float*)&hp[kq + 1][cp])[hf] = hv.y;
        ((float*)&hp[kq + 2][cp])[hf] = hv.z;
        ((float*)&hp[kq + 3][cp])[hf] = hv.w;
    }
    __syncthreads();

    for (int v = tid; v < NVOCAB; v += 256) {
        u64 acc[16];
        const u64 bia = dup2(__ldg(&b_out[v]));
        #pragma unroll
        for (int cp = 0; cp < 16; ++cp) acc[cp] = bia;
        #pragma unroll
        for (int k = 0; k < 32; ++k) {
            const u64 wv = dup2(__ldg(&g_wvt[k * NVOCAB + v]));
            const ulonglong2* hk = (const ulonglong2*)hp[k];
            #pragma unroll
            for (int qq = 0; qq < 8; ++qq) {
                ulonglong2 h2 = hk[qq];
                acc[2 * qq + 0] = fma2(wv, h2.x, acc[2 * qq + 0]);
                acc[2 * qq + 1] = fma2(wv, h2.y, acc[2 * qq + 1]);
            }
        }
        #pragma unroll
        for (int cp = 0; cp < 16; ++cp) {
            int rt_i = cp >> 2, bpp = cp & 3;
            long rt = rt0 + rt_i;
            long bb0 = half * 8 + 2 * bpp;
            float2 o = unpk(acc[cp]);
            outp[(bb0 * (NROWS * NT) + rt) * NVOCAB + v] = o.x;
            outp[((bb0 + 1) * (NROWS * NT) + rt) * NVOCAB + v] = o.y;
        }
    }
}

// ---------------- launch: positions (1 prep, 2 reset, 3 noop, 4 rnn, 5 out) ----------------
extern "C" void kernel_launch(void* const* d_in, const int* in_sizes, int n_in,
                              void* d_out, int out_size)
{
    (void)in_sizes; (void)n_in; (void)out_size;
    const int*   x     = (const int*)  d_in[0];
    const float* embed = (const float*)d_in[1];
    const float* wih0  = (const float*)d_in[2];
    const float* whh0  = (const float*)d_in[3];
    const float* bih0  = (const float*)d_in[4];
    const float* bhh0  = (const float*)d_in[5];
    const float* wih1  = (const float*)d_in[6];
    const float* whh1  = (const float*)d_in[7];
    const float* bih1  = (const float*)d_in[8];
    const float* bhh1  = (const float*)d_in[9];
    const float* wih2  = (const float*)d_in[10];
    const float* whh2  = (const float*)d_in[11];
    const float* bih2  = (const float*)d_in[12];
    const float* bhh2  = (const float*)d_in[13];
    const float* w_h2e = (const float*)d_in[14];
    const float* b_h2e = (const float*)d_in[15];
    const float* w_out = (const float*)d_in[16];
    const float* b_out = (const float*)d_in[17];
    float* outp = (float*)d_out;

    cudaFuncSetAttribute(rnn_kernel, cudaFuncAttributeMaxDynamicSharedMemorySize, SMEM_RNN);

    prep_kernel<<<260, 96>>>(embed, wih0, whh0, wih1, whh1, wih2, whh2,
                             w_h2e, b_h2e, bih0, w_out);
    reset_kernel<<<1, 128>>>();
    noop_kernel<<<1, 32>>>();
    rnn_kernel<<<NROWS, 256, SMEM_RNN>>>(x, bhh0, bih1, bhh1, bih2, bhh2);
    out_kernel<<<(NROWS * NT / 4) * 2, 256>>>(outp, b_out);
}

// round 15
// speedup vs baseline: 1.1731x; 1.0569x over previous
#include <cuda_runtime.h>
#include <cstdint>

#define NB     16
#define NROWS  128
#define NT     128
#define NVOCAB 258
typedef unsigned long long u64;

// ---------------- static device scratch ----------------
__device__ __align__(16) float  g_proj[NVOCAB * 96];
__device__ __align__(16) float4 g_w4[3 * 2 * 3 * 8 * 32];    // [l][side][gate][chunk][j]
__device__ __align__(16) float  g_cbias[96];
__device__ __align__(16) float  g_w64[96];
__device__ __align__(16) float  g_wvt[32 * NVOCAB];          // w_out^T [k][v]
__device__ __align__(16) float  g_hout[NROWS * NT * 16 * 32]; // [rt][b][j]
__device__ int g_flag[NROWS * 2];

// ---------------- helpers ----------------
__device__ __forceinline__ int ld_rlx(const int* p) {
    int v; asm volatile("ld.relaxed.gpu.global.s32 %0, [%1];" : "=r"(v) : "l"(p) : "memory"); return v;
}
__device__ __forceinline__ void fence_acq() {
    asm volatile("fence.acq_rel.gpu;" ::: "memory");
}
__device__ __forceinline__ void st_rel(int* p, int v) {
    asm volatile("st.release.gpu.s32 [%0], %1;" :: "l"(p), "r"(v) : "memory");
}
__device__ __forceinline__ u64 dup2(float x) {
    u64 r; unsigned xi = __float_as_uint(x);
    asm("mov.b64 %0, {%1, %1};" : "=l"(r) : "r"(xi)); return r;
}
__device__ __forceinline__ u64 pack2(float a, float b) {
    u64 r; asm("mov.b64 %0, {%1, %2};" : "=l"(r) : "r"(__float_as_uint(a)), "r"(__float_as_uint(b)));
    return r;
}
__device__ __forceinline__ float2 unpk(u64 v) {
    unsigned lo, hi; asm("mov.b64 {%0, %1}, %2;" : "=r"(lo), "=r"(hi) : "l"(v));
    return make_float2(__uint_as_float(lo), __uint_as_float(hi));
}
__device__ __forceinline__ u64 fma2(u64 a, u64 b, u64 c) {
    u64 d; asm("fma.rn.f32x2 %0, %1, %2, %3;" : "=l"(d) : "l"(a), "l"(b), "l"(c)); return d;
}
__device__ __forceinline__ float tanh_ap(float x) {
    float y; asm("tanh.approx.f32 %0, %1;" : "=f"(y) : "f"(x)); return y;
}
__device__ __forceinline__ float sig_ap(float x) { return fmaf(tanh_ap(x * 0.5f), 0.5f, 0.5f); }

// ---------------- prep ----------------
__global__ void prep_kernel(
    const float* __restrict__ embed,
    const float* __restrict__ wih0, const float* __restrict__ whh0,
    const float* __restrict__ wih1, const float* __restrict__ whh1,
    const float* __restrict__ wih2, const float* __restrict__ whh2,
    const float* __restrict__ w_h2e, const float* __restrict__ b_h2e,
    const float* __restrict__ bih0, const float* __restrict__ w_out)
{
    const int v = blockIdx.x;
    const int g = threadIdx.x;       // 0..95
    if (v < NVOCAB) {
        float s = 0.0f;
        #pragma unroll 8
        for (int e = 0; e < 64; ++e) s = fmaf(embed[v * 64 + e], wih0[g * 65 + e], s);
        g_proj[v * 96 + g] = s;
    } else if (v == NVOCAB) {
        const int gate = g >> 5, j = g & 31;
        float cb = bih0[g];
        for (int e = 0; e < 65; ++e) cb = fmaf(wih0[g * 65 + e], b_h2e[e], cb);
        g_cbias[g] = cb;
        g_w64[g] = wih0[g * 65 + 64];
        float wc[32];
        #pragma unroll
        for (int k = 0; k < 32; ++k) {
            float s = 0.0f;
            for (int e = 0; e < 65; ++e) s = fmaf(wih0[g * 65 + e], w_h2e[e * 32 + k], s);
            wc[k] = s;
        }
        const float* Wm[3][2] = {{0, whh0}, {wih1, whh1}, {wih2, whh2}};
        #pragma unroll
        for (int c = 0; c < 8; ++c) {
            g_w4[(((0 * 2 + 0) * 3 + gate) * 8 + c) * 32 + j] =
                make_float4(wc[4*c], wc[4*c+1], wc[4*c+2], wc[4*c+3]);
            for (int l = 0; l < 3; ++l)
                for (int s_ = 0; s_ < 2; ++s_) {
                    const float* W = Wm[l][s_];
                    if (!W) continue;
                    g_w4[(((l * 2 + s_) * 3 + gate) * 8 + c) * 32 + j] =
                        make_float4(W[g*32+4*c], W[g*32+4*c+1], W[g*32+4*c+2], W[g*32+4*c+3]);
                }
        }
    } else {
        for (int i = g; i < 32 * NVOCAB; i += 96) {
            int k = i / NVOCAB, vv = i % NVOCAB;
            g_wvt[i] = w_out[vv * 32 + k];
        }
    }
}

__global__ void reset_kernel() {
    int i = threadIdx.x;
    if (i < NROWS * 2) g_flag[i] = 0;
}

__global__ void noop_kernel() {}   // pad launch position so rnn lands at slot 4 for ncu

// ---------------- one GRU layer from smem weights; k-pair f32x2, 2 batches/thread ----------------
__device__ __forceinline__ void layer_step(
    const float* __restrict__ wsl,            // layer base (6144 floats)
    const float* __restrict__ insm,           // [2][4][36]
    const float* __restrict__ hq,             // [2][4][36]
    float* __restrict__ hp,                   // [2][4][36]
    int j, int bp,
    float cr, float cz, float cn, float ch,
    float ar0, float ar1, float az0, float az1, float an0, float an1,
    float* __restrict__ hold)
{
    const ulonglong2* wir = (const ulonglong2*)(wsl)        + j;
    const ulonglong2* wiz = (const ulonglong2*)(wsl + 1024) + j;
    const ulonglong2* win = (const ulonglong2*)(wsl + 2048) + j;
    const ulonglong2* whr = (const ulonglong2*)(wsl + 3072) + j;
    const ulonglong2* whz = (const ulonglong2*)(wsl + 4096) + j;
    const ulonglong2* whn = (const ulonglong2*)(wsl + 5120) + j;
    u64 ar[2] = { pack2(cr + ar0, 0.f), pack2(cr + ar1, 0.f) };
    u64 az[2] = { pack2(cz + az0, 0.f), pack2(cz + az1, 0.f) };
    u64 ai[2] = { pack2(cn + an0, 0.f), pack2(cn + an1, 0.f) };
    u64 ah[2] = { pack2(ch, 0.f),       pack2(ch, 0.f) };
    const int row0 = bp * 36;              // bi=0 half
    const int row1 = (4 + bp) * 36;        // bi=1 half
    #pragma unroll
    for (int c = 0; c < 8; ++c) {
        ulonglong2 w_ir = wir[c * 32];
        ulonglong2 w_iz = wiz[c * 32];
        ulonglong2 w_in = win[c * 32];
        ulonglong2 w_hr = whr[c * 32];
        ulonglong2 w_hz = whz[c * 32];
        ulonglong2 w_hn = whn[c * 32];
        #pragma unroll
        for (int bi = 0; bi < 2; ++bi) {
            const int ro = bi ? row1 : row0;
            ulonglong2 xv = *(const ulonglong2*)&insm[ro + 4 * c];
            ulonglong2 hv = *(const ulonglong2*)&hq[ro + 4 * c];
            ar[bi] = fma2(w_ir.x, xv.x, ar[bi]); ar[bi] = fma2(w_ir.y, xv.y, ar[bi]);
            ar[bi] = fma2(w_hr.x, hv.x, ar[bi]); ar[bi] = fma2(w_hr.y, hv.y, ar[bi]);
            az[bi] = fma2(w_iz.x, xv.x, az[bi]); az[bi] = fma2(w_iz.y, xv.y, az[bi]);
            az[bi] = fma2(w_hz.x, hv.x, az[bi]); az[bi] = fma2(w_hz.y, hv.y, az[bi]);
            ai[bi] = fma2(w_in.x, xv.x, ai[bi]); ai[bi] = fma2(w_in.y, xv.y, ai[bi]);
            ah[bi] = fma2(w_hn.x, hv.x, ah[bi]); ah[bi] = fma2(w_hn.y, hv.y, ah[bi]);
        }
    }
    #pragma unroll
    for (int bi = 0; bi < 2; ++bi) {
        float2 fr = unpk(ar[bi]), fz = unpk(az[bi]);
        float2 fi = unpk(ai[bi]), fh = unpk(ah[bi]);
        float rr = sig_ap(fr.x + fr.y), zz = sig_ap(fz.x + fz.y);
        float nn = tanh_ap(fmaf(rr, fh.x + fh.y, fi.x + fi.y));
        float hv = fmaf(zz, hold[bi] - nn, nn);
        hold[bi] = hv;
        hp[(bi ? row1 : row0) + j] = hv;
    }
}

// ---------------- persistent wavefront: CTA=(row, half8), 128 thr, 2 CTAs/SM ----------------
// dyn smem (bytes): ws 73728 | prevsh 1152 | hbuf 6912 | toksh 4128  = 85920
#define SMEM_RNN 85920
__global__ __launch_bounds__(128) void rnn_kernel(
    const int* __restrict__ x,
    const float* __restrict__ bhh0,
    const float* __restrict__ bih1, const float* __restrict__ bhh1,
    const float* __restrict__ bih2, const float* __restrict__ bhh2)
{
    extern __shared__ __align__(16) char smem[];
    float* ws     = (float*)smem;                              // 18432 floats
    float* prevsh = (float*)(smem + 73728);                    // [2][4][36]
    float* hbuf   = (float*)(smem + 73728 + 1152);             // [6][2][4][36]
    int*   toksh  = (int*)  (smem + 73728 + 1152 + 6912);      // [8][129]

    const int tid  = threadIdx.x;
    const int j    = tid >> 2;        // unit 0..31
    const int bp   = tid & 3;         // batch pair 0..3 (local batches 2bp, 2bp+1)
    const int r    = blockIdx.x >> 1;
    const int half = blockIdx.x & 1;

    // prologue: weights + tokens -> smem; zero buffers
    for (int idx = tid; idx < 4608; idx += 128)
        ((float4*)ws)[idx] = ((const float4*)g_w4)[idx];
    for (int idx = tid; idx < 8 * 128; idx += 128) {
        int lb = idx >> 7, tt = idx & 127;
        toksh[lb * 129 + tt] = x[(half * 8 + lb) * (NROWS * NT) + r * NT + tt];
    }
    for (int idx = tid; idx < 288; idx += 128) prevsh[idx] = 0.f;
    for (int idx = tid; idx < 6 * 288; idx += 128) hbuf[idx] = 0.f;

    const float rf = (float)r * (2.f / 128.f) - 1.f;
    const float c_r0 = fmaf(rf, g_w64[j],      g_cbias[j])      + bhh0[j];
    const float c_z0 = fmaf(rf, g_w64[32 + j], g_cbias[32 + j]) + bhh0[32 + j];
    const float c_n0 = fmaf(rf, g_w64[64 + j], g_cbias[64 + j]);
    const float c_h0 = bhh0[64 + j];
    const float c_r1 = bih1[j] + bhh1[j];
    const float c_z1 = bih1[32 + j] + bhh1[32 + j];
    const float c_n1 = bih1[64 + j];
    const float c_h1 = bhh1[64 + j];
    const float c_r2 = bih2[j] + bhh2[j];
    const float c_z2 = bih2[32 + j] + bhh2[32 + j];
    const float c_n2 = bih2[64 + j];
    const float c_h2 = bhh2[64 + j];

    float h0old[2] = {0.f, 0.f}, h1old[2] = {0.f, 0.f}, h2old[2] = {0.f, 0.f};

    int*       myflag   = &g_flag[r * 2 + half];
    const int* prevflag = &g_flag[(r - 1) * 2 + half];
    __syncthreads();

    for (int t = 0; t < NT; ++t) {
        const int p = t & 1, q = p ^ 1;
        const int tk0 = toksh[(2 * bp + 0) * 129 + t];
        const int tk1 = toksh[(2 * bp + 1) * 129 + t];
        // proj via L1 (R12 proved residency irrelevant); issued before the wait
        const float pr0 = __ldg(&g_proj[tk0 * 96 + j]);
        const float pz0 = __ldg(&g_proj[tk0 * 96 + 32 + j]);
        const float pn0 = __ldg(&g_proj[tk0 * 96 + 64 + j]);
        const float pr1 = __ldg(&g_proj[tk1 * 96 + j]);
        const float pz1 = __ldg(&g_proj[tk1 * 96 + 32 + j]);
        const float pn1 = __ldg(&g_proj[tk1 * 96 + 64 + j]);

        if (r > 0) {
            // leader-spin: relaxed poll, ONE acquire fence, barrier propagates
            if (tid == 0) {
                while (ld_rlx(prevflag) < t + 1) { }
                fence_acq();
            }
            __syncthreads();                                   // bar A1
            if (tid < 64) {
                // float4 idx covers local batch lb = tid>>3, chunk qq = tid&7
                float4 pv = __ldcg(&((const float4*)g_hout)[((r - 1) * NT + t) * 128 +
                                                            half * 64 + tid]);
                int lb = tid >> 3, qq = tid & 7;
                *(float4*)&prevsh[((lb & 1) * 4 + (lb >> 1)) * 36 + 4 * qq] = pv;
            }
        }
        __syncthreads();                                       // bar A2

        layer_step(ws,         prevsh,                   hbuf + (0 * 2 + q) * 288, hbuf + (0 * 2 + p) * 288,
                   j, bp, c_r0, c_z0, c_n0, c_h0, pr0, pr1, pz0, pz1, pn0, pn1, h0old);
        __syncthreads();                                       // bar B
        layer_step(ws + 6144,  hbuf + (0 * 2 + p) * 288, hbuf + (1 * 2 + q) * 288, hbuf + (1 * 2 + p) * 288,
                   j, bp, c_r1, c_z1, c_n1, c_h1, 0.f, 0.f, 0.f, 0.f, 0.f, 0.f, h1old);
        __syncthreads();                                       // bar C
        layer_step(ws + 12288, hbuf + (1 * 2 + p) * 288, hbuf + (2 * 2 + q) * 288, hbuf + (2 * 2 + p) * 288,
                   j, bp, c_r2, c_z2, c_n2, c_h2, 0.f, 0.f, 0.f, 0.f, 0.f, 0.f, h2old);

        __stcg(&g_hout[(r * NT + t) * 512 + (half * 8 + 2 * bp + 0) * 32 + j], h2old[0]);
        __stcg(&g_hout[(r * NT + t) * 512 + (half * 8 + 2 * bp + 1) * 32 + j], h2old[1]);
        __syncthreads();                                       // bar D
        if (tid == 0) st_rel(myflag, t + 1);
    }
}

// ---------------- epilogue: block = (half, 4 rt-cells), thread = vocab scalar ----------------
__global__ __launch_bounds__(256) void out_kernel(
    float* __restrict__ outp, const float* __restrict__ b_out)
{
    __shared__ __align__(16) u64 hp[32][16];   // [k][cp]; cp = rt_i*4 + bpair
    const int tid  = threadIdx.x;
    const int half = blockIdx.x & 1;
    const int rt0  = (blockIdx.x >> 1) * 4;

    {
        int rt_i = tid >> 6, rem = tid & 63;
        float4 hv = __ldcg(&((const float4*)g_hout)[(rt0 + rt_i) * 128 +
                                                    (half * 8 + (rem >> 3)) * 8 + (rem & 7)]);
        int b = rem >> 3, kq = (rem & 7) * 4;
        int cp = rt_i * 4 + (b >> 1), hf = b & 1;
        ((float*)&hp[kq + 0][cp])[hf] = hv.x;
        ((float*)&hp[kq + 1][cp])[hf] = hv.y;
        ((float*)&hp[kq + 2][cp])[hf] = hv.z;
        ((float*)&hp[kq + 3][cp])[hf] = hv.w;
    }
    __syncthreads();

    for (int v = tid; v < NVOCAB; v += 256) {
        u64 acc[16];
        const u64 bia = dup2(__ldg(&b_out[v]));
        #pragma unroll
        for (int cp = 0; cp < 16; ++cp) acc[cp] = bia;
        #pragma unroll
        for (int k = 0; k < 32; ++k) {
            const u64 wv = dup2(__ldg(&g_wvt[k * NVOCAB + v]));
            const ulonglong2* hk = (const ulonglong2*)hp[k];
            #pragma unroll
            for (int qq = 0; qq < 8; ++qq) {
                ulonglong2 h2 = hk[qq];
                acc[2 * qq + 0] = fma2(wv, h2.x, acc[2 * qq + 0]);
                acc[2 * qq + 1] = fma2(wv, h2.y, acc[2 * qq + 1]);
            }
        }
        #pragma unroll
        for (int cp = 0; cp < 16; ++cp) {
            int rt_i = cp >> 2, bpp = cp & 3;
            long rt = rt0 + rt_i;
            long bb0 = half * 8 + 2 * bpp;
            float2 o = unpk(acc[cp]);
            outp[(bb0 * (NROWS * NT) + rt) * NVOCAB + v] = o.x;
            outp[((bb0 + 1) * (NROWS * NT) + rt) * NVOCAB + v] = o.y;
        }
    }
}

// ---------------- launch: positions (1 prep, 2 reset, 3 noop, 4 rnn, 5 out) ----------------
extern "C" void kernel_launch(void* const* d_in, const int* in_sizes, int n_in,
                              void* d_out, int out_size)
{
    (void)in_sizes; (void)n_in; (void)out_size;
    const int*   x     = (const int*)  d_in[0];
    const float* embed = (const float*)d_in[1];
    const float* wih0  = (const float*)d_in[2];
    const float* whh0  = (const float*)d_in[3];
    const float* bih0  = (const float*)d_in[4];
    const float* bhh0  = (const float*)d_in[5];
    const float* wih1  = (const float*)d_in[6];
    const float* whh1  = (const float*)d_in[7];
    const float* bih1  = (const float*)d_in[8];
    const float* bhh1  = (const float*)d_in[9];
    const float* wih2  = (const float*)d_in[10];
    const float* whh2  = (const float*)d_in[11];
    const float* bih2  = (const float*)d_in[12];
    const float* bhh2  = (const float*)d_in[13];
    const float* w_h2e = (const float*)d_in[14];
    const float* b_h2e = (const float*)d_in[15];
    const float* w_out = (const float*)d_in[16];
    const float* b_out = (const float*)d_in[17];
    float* outp = (float*)d_out;

    cudaFuncSetAttribute(rnn_kernel, cudaFuncAttributeMaxDynamicSharedMemorySize, SMEM_RNN);

    prep_kernel<<<260, 96>>>(embed, wih0, whh0, wih1, whh1, wih2, whh2,
                             w_h2e, b_h2e, bih0, w_out);
    reset_kernel<<<1, 256>>>();
    noop_kernel<<<1, 32>>>();
    rnn_kernel<<<NROWS * 2, 128, SMEM_RNN>>>(x, bhh0, bih1, bhh1, bih2, bhh2);
    out_kernel<<<(NROWS * NT / 4) * 2, 256>>>(outp, b_out);
}

// round 16
// speedup vs baseline: 1.1786x; 1.0047x over previous
#include <cuda_runtime.h>
#include <cstdint>

#define NB     16
#define NROWS  128
#define NT     128
#define NVOCAB 258
typedef unsigned long long u64;

// ---------------- static device scratch ----------------
__device__ __align__(16) float  g_proj[NVOCAB * 96];
__device__ __align__(16) float4 g_w4[3 * 2 * 3 * 8 * 32];    // [l][side][gate][chunk][j]
__device__ __align__(16) float  g_cbias[96];
__device__ __align__(16) float  g_w64[96];
__device__ __align__(16) float  g_wvt[32 * NVOCAB];          // w_out^T [k][v]
__device__ __align__(16) float  g_hout[NROWS * NT * 16 * 32]; // [rt][b][j]
__device__ int g_flag[NROWS * 2];

// ---------------- helpers ----------------
__device__ __forceinline__ int ld_rlx(const int* p) {
    int v; asm volatile("ld.relaxed.gpu.global.s32 %0, [%1];" : "=r"(v) : "l"(p) : "memory"); return v;
}
__device__ __forceinline__ void fence_acq() {
    asm volatile("fence.acq_rel.gpu;" ::: "memory");
}
__device__ __forceinline__ void st_rel(int* p, int v) {
    asm volatile("st.release.gpu.s32 [%0], %1;" :: "l"(p), "r"(v) : "memory");
}
__device__ __forceinline__ u64 dup2(float x) {
    u64 r; unsigned xi = __float_as_uint(x);
    asm("mov.b64 %0, {%1, %1};" : "=l"(r) : "r"(xi)); return r;
}
__device__ __forceinline__ u64 pack2(float a, float b) {
    u64 r; asm("mov.b64 %0, {%1, %2};" : "=l"(r) : "r"(__float_as_uint(a)), "r"(__float_as_uint(b)));
    return r;
}
__device__ __forceinline__ float2 unpk(u64 v) {
    unsigned lo, hi; asm("mov.b64 {%0, %1}, %2;" : "=r"(lo), "=r"(hi) : "l"(v));
    return make_float2(__uint_as_float(lo), __uint_as_float(hi));
}
__device__ __forceinline__ u64 fma2(u64 a, u64 b, u64 c) {
    u64 d; asm("fma.rn.f32x2 %0, %1, %2, %3;" : "=l"(d) : "l"(a), "l"(b), "l"(c)); return d;
}
__device__ __forceinline__ float tanh_ap(float x) {
    float y; asm("tanh.approx.f32 %0, %1;" : "=f"(y) : "f"(x)); return y;
}
__device__ __forceinline__ float sig_ap(float x) { return fmaf(tanh_ap(x * 0.5f), 0.5f, 0.5f); }

// ---------------- prep ----------------
__global__ void prep_kernel(
    const float* __restrict__ embed,
    const float* __restrict__ wih0, const float* __restrict__ whh0,
    const float* __restrict__ wih1, const float* __restrict__ whh1,
    const float* __restrict__ wih2, const float* __restrict__ whh2,
    const float* __restrict__ w_h2e, const float* __restrict__ b_h2e,
    const float* __restrict__ bih0, const float* __restrict__ w_out)
{
    const int v = blockIdx.x;
    const int g = threadIdx.x;       // 0..95
    if (v < NVOCAB) {
        float s = 0.0f;
        #pragma unroll 8
        for (int e = 0; e < 64; ++e) s = fmaf(embed[v * 64 + e], wih0[g * 65 + e], s);
        g_proj[v * 96 + g] = s;
    } else if (v == NVOCAB) {
        const int gate = g >> 5, j = g & 31;
        float cb = bih0[g];
        for (int e = 0; e < 65; ++e) cb = fmaf(wih0[g * 65 + e], b_h2e[e], cb);
        g_cbias[g] = cb;
        g_w64[g] = wih0[g * 65 + 64];
        float wc[32];
        #pragma unroll
        for (int k = 0; k < 32; ++k) {
            float s = 0.0f;
            for (int e = 0; e < 65; ++e) s = fmaf(wih0[g * 65 + e], w_h2e[e * 32 + k], s);
            wc[k] = s;
        }
        const float* Wm[3][2] = {{0, whh0}, {wih1, whh1}, {wih2, whh2}};
        #pragma unroll
        for (int c = 0; c < 8; ++c) {
            g_w4[(((0 * 2 + 0) * 3 + gate) * 8 + c) * 32 + j] =
                make_float4(wc[4*c], wc[4*c+1], wc[4*c+2], wc[4*c+3]);
            for (int l = 0; l < 3; ++l)
                for (int s_ = 0; s_ < 2; ++s_) {
                    const float* W = Wm[l][s_];
                    if (!W) continue;
                    g_w4[(((l * 2 + s_) * 3 + gate) * 8 + c) * 32 + j] =
                        make_float4(W[g*32+4*c], W[g*32+4*c+1], W[g*32+4*c+2], W[g*32+4*c+3]);
                }
        }
    } else {
        for (int i = g; i < 32 * NVOCAB; i += 96) {
            int k = i / NVOCAB, vv = i % NVOCAB;
            g_wvt[i] = w_out[vv * 32 + k];
        }
    }
}

__global__ void reset_kernel() {
    int i = threadIdx.x;
    if (i < NROWS * 2) g_flag[i] = 0;
}

__global__ void noop_kernel() {}   // pad launch position so rnn lands at slot 4 for ncu

// ---------------- pipelined GRU layer: A/B register staging over c ----------------
// FMA block on one staged operand set (both batch halves)
#define FMA_BLK(W0,W1,W2,W3,W4,W5,X0,H0,X1,H1)                          \
    ar0 = fma2(W0.x, X0.x, ar0); ar0 = fma2(W0.y, X0.y, ar0);           \
    az0 = fma2(W1.x, X0.x, az0); az0 = fma2(W1.y, X0.y, az0);           \
    ai0 = fma2(W2.x, X0.x, ai0); ai0 = fma2(W2.y, X0.y, ai0);           \
    ar0 = fma2(W3.x, H0.x, ar0); ar0 = fma2(W3.y, H0.y, ar0);           \
    az0 = fma2(W4.x, H0.x, az0); az0 = fma2(W4.y, H0.y, az0);           \
    ah0 = fma2(W5.x, H0.x, ah0); ah0 = fma2(W5.y, H0.y, ah0);           \
    ar1 = fma2(W0.x, X1.x, ar1); ar1 = fma2(W0.y, X1.y, ar1);           \
    az1 = fma2(W1.x, X1.x, az1); az1 = fma2(W1.y, X1.y, az1);           \
    ai1 = fma2(W2.x, X1.x, ai1); ai1 = fma2(W2.y, X1.y, ai1);           \
    ar1 = fma2(W3.x, H1.x, ar1); ar1 = fma2(W3.y, H1.y, ar1);           \
    az1 = fma2(W4.x, H1.x, az1); az1 = fma2(W4.y, H1.y, az1);           \
    ah1 = fma2(W5.x, H1.x, ah1); ah1 = fma2(W5.y, H1.y, ah1);

#define LOAD_BLK(W0,W1,W2,W3,W4,W5,X0,H0,X1,H1,cc)                      \
    W0 = wir[(cc) * 32]; W1 = wiz[(cc) * 32]; W2 = win[(cc) * 32];      \
    W3 = whr[(cc) * 32]; W4 = whz[(cc) * 32]; W5 = whn[(cc) * 32];      \
    X0 = *(const ulonglong2*)&insm[row0 + 4 * (cc)];                    \
    H0 = *(const ulonglong2*)&hq[row0 + 4 * (cc)];                      \
    X1 = *(const ulonglong2*)&insm[row1 + 4 * (cc)];                    \
    H1 = *(const ulonglong2*)&hq[row1 + 4 * (cc)];

__device__ __forceinline__ void layer_step(
    const float* __restrict__ wsl,            // layer base (6144 floats)
    const float* __restrict__ insm,           // [2][4][36]
    const float* __restrict__ hq,             // [2][4][36]
    float* __restrict__ hp,                   // [2][4][36]
    int j, int bp,
    float cr, float cz, float cn, float ch,
    float ar0i, float ar1i, float az0i, float az1i, float an0i, float an1i,
    float* __restrict__ hold)
{
    const ulonglong2* wir = (const ulonglong2*)(wsl)        + j;
    const ulonglong2* wiz = (const ulonglong2*)(wsl + 1024) + j;
    const ulonglong2* win = (const ulonglong2*)(wsl + 2048) + j;
    const ulonglong2* whr = (const ulonglong2*)(wsl + 3072) + j;
    const ulonglong2* whz = (const ulonglong2*)(wsl + 4096) + j;
    const ulonglong2* whn = (const ulonglong2*)(wsl + 5120) + j;
    u64 ar0 = pack2(cr + ar0i, 0.f), ar1 = pack2(cr + ar1i, 0.f);
    u64 az0 = pack2(cz + az0i, 0.f), az1 = pack2(cz + az1i, 0.f);
    u64 ai0 = pack2(cn + an0i, 0.f), ai1 = pack2(cn + an1i, 0.f);
    u64 ah0 = pack2(ch, 0.f),        ah1 = pack2(ch, 0.f);
    const int row0 = bp * 36;              // bi=0 half
    const int row1 = (4 + bp) * 36;        // bi=1 half

    ulonglong2 wA0, wA1, wA2, wA3, wA4, wA5, xA0, hA0, xA1, hA1;
    ulonglong2 wB0, wB1, wB2, wB3, wB4, wB5, xB0, hB0, xB1, hB1;

    LOAD_BLK(wA0, wA1, wA2, wA3, wA4, wA5, xA0, hA0, xA1, hA1, 0)
    #pragma unroll
    for (int c = 0; c < 8; ++c) {
        if ((c & 1) == 0) {
            if (c < 7) { LOAD_BLK(wB0, wB1, wB2, wB3, wB4, wB5, xB0, hB0, xB1, hB1, c + 1) }
            FMA_BLK(wA0, wA1, wA2, wA3, wA4, wA5, xA0, hA0, xA1, hA1)
        } else {
            if (c < 7) { LOAD_BLK(wA0, wA1, wA2, wA3, wA4, wA5, xA0, hA0, xA1, hA1, c + 1) }
            FMA_BLK(wB0, wB1, wB2, wB3, wB4, wB5, xB0, hB0, xB1, hB1)
        }
    }

    {
        float2 fr = unpk(ar0), fz = unpk(az0), fi = unpk(ai0), fh = unpk(ah0);
        float rr = sig_ap(fr.x + fr.y), zz = sig_ap(fz.x + fz.y);
        float nn = tanh_ap(fmaf(rr, fh.x + fh.y, fi.x + fi.y));
        float hv = fmaf(zz, hold[0] - nn, nn);
        hold[0] = hv;
        hp[row0 + j] = hv;
    }
    {
        float2 fr = unpk(ar1), fz = unpk(az1), fi = unpk(ai1), fh = unpk(ah1);
        float rr = sig_ap(fr.x + fr.y), zz = sig_ap(fz.x + fz.y);
        float nn = tanh_ap(fmaf(rr, fh.x + fh.y, fi.x + fi.y));
        float hv = fmaf(zz, hold[1] - nn, nn);
        hold[1] = hv;
        hp[row1 + j] = hv;
    }
}

// ---------------- persistent wavefront: CTA=(row, half8), 128 thr, 2 CTAs/SM ----------------
// dyn smem (bytes): ws 73728 | prevsh 1152 | hbuf 6912 | toksh 4128  = 85920
#define SMEM_RNN 85920
__global__ __launch_bounds__(128) void rnn_kernel(
    const int* __restrict__ x,
    const float* __restrict__ bhh0,
    const float* __restrict__ bih1, const float* __restrict__ bhh1,
    const float* __restrict__ bih2, const float* __restrict__ bhh2)
{
    extern __shared__ __align__(16) char smem[];
    float* ws     = (float*)smem;                              // 18432 floats
    float* prevsh = (float*)(smem + 73728);                    // [2][4][36]
    float* hbuf   = (float*)(smem + 73728 + 1152);             // [6][2][4][36]
    int*   toksh  = (int*)  (smem + 73728 + 1152 + 6912);      // [8][129]

    const int tid  = threadIdx.x;
    const int j    = tid >> 2;        // unit 0..31
    const int bp   = tid & 3;         // batch pair 0..3 (local batches 2bp, 2bp+1)
    const int r    = blockIdx.x >> 1;
    const int half = blockIdx.x & 1;

    // prologue: weights + tokens -> smem; zero buffers
    for (int idx = tid; idx < 4608; idx += 128)
        ((float4*)ws)[idx] = ((const float4*)g_w4)[idx];
    for (int idx = tid; idx < 8 * 128; idx += 128) {
        int lb = idx >> 7, tt = idx & 127;
        toksh[lb * 129 + tt] = x[(half * 8 + lb) * (NROWS * NT) + r * NT + tt];
    }
    for (int idx = tid; idx < 288; idx += 128) prevsh[idx] = 0.f;
    for (int idx = tid; idx < 6 * 288; idx += 128) hbuf[idx] = 0.f;

    const float rf = (float)r * (2.f / 128.f) - 1.f;
    const float c_r0 = fmaf(rf, g_w64[j],      g_cbias[j])      + bhh0[j];
    const float c_z0 = fmaf(rf, g_w64[32 + j], g_cbias[32 + j]) + bhh0[32 + j];
    const float c_n0 = fmaf(rf, g_w64[64 + j], g_cbias[64 + j]);
    const float c_h0 = bhh0[64 + j];
    const float c_r1 = bih1[j] + bhh1[j];
    const float c_z1 = bih1[32 + j] + bhh1[32 + j];
    const float c_n1 = bih1[64 + j];
    const float c_h1 = bhh1[64 + j];
    const float c_r2 = bih2[j] + bhh2[j];
    const float c_z2 = bih2[32 + j] + bhh2[32 + j];
    const float c_n2 = bih2[64 + j];
    const float c_h2 = bhh2[64 + j];

    float h0old[2] = {0.f, 0.f}, h1old[2] = {0.f, 0.f}, h2old[2] = {0.f, 0.f};

    int*       myflag   = &g_flag[r * 2 + half];
    const int* prevflag = &g_flag[(r - 1) * 2 + half];
    __syncthreads();

    for (int t = 0; t < NT; ++t) {
        const int p = t & 1, q = p ^ 1;
        const int tk0 = toksh[(2 * bp + 0) * 129 + t];
        const int tk1 = toksh[(2 * bp + 1) * 129 + t];
        // proj via L1; issued before the wait (latency buried in poll)
        const float pr0 = __ldg(&g_proj[tk0 * 96 + j]);
        const float pz0 = __ldg(&g_proj[tk0 * 96 + 32 + j]);
        const float pn0 = __ldg(&g_proj[tk0 * 96 + 64 + j]);
        const float pr1 = __ldg(&g_proj[tk1 * 96 + j]);
        const float pz1 = __ldg(&g_proj[tk1 * 96 + 32 + j]);
        const float pn1 = __ldg(&g_proj[tk1 * 96 + 64 + j]);

        if (r > 0) {
            // leader-spin: relaxed poll, ONE acquire fence, barrier propagates
            if (tid == 0) {
                while (ld_rlx(prevflag) < t + 1) { }
                fence_acq();
            }
            __syncthreads();                                   // bar A1
            if (tid < 64) {
                float4 pv = __ldcg(&((const float4*)g_hout)[((r - 1) * NT + t) * 128 +
                                                            half * 64 + tid]);
                int lb = tid >> 3, qq = tid & 7;
                *(float4*)&prevsh[((lb & 1) * 4 + (lb >> 1)) * 36 + 4 * qq] = pv;
            }
        }
        __syncthreads();                                       // bar A2

        layer_step(ws,         prevsh,                   hbuf + (0 * 2 + q) * 288, hbuf + (0 * 2 + p) * 288,
                   j, bp, c_r0, c_z0, c_n0, c_h0, pr0, pr1, pz0, pz1, pn0, pn1, h0old);
        __syncthreads();                                       // bar B
        layer_step(ws + 6144,  hbuf + (0 * 2 + p) * 288, hbuf + (1 * 2 + q) * 288, hbuf + (1 * 2 + p) * 288,
                   j, bp, c_r1, c_z1, c_n1, c_h1, 0.f, 0.f, 0.f, 0.f, 0.f, 0.f, h1old);
        __syncthreads();                                       // bar C
        layer_step(ws + 12288, hbuf + (1 * 2 + p) * 288, hbuf + (2 * 2 + q) * 288, hbuf + (2 * 2 + p) * 288,
                   j, bp, c_r2, c_z2, c_n2, c_h2, 0.f, 0.f, 0.f, 0.f, 0.f, 0.f, h2old);

        __stcg(&g_hout[(r * NT + t) * 512 + (half * 8 + 2 * bp + 0) * 32 + j], h2old[0]);
        __stcg(&g_hout[(r * NT + t) * 512 + (half * 8 + 2 * bp + 1) * 32 + j], h2old[1]);
        __syncthreads();                                       // bar D
        if (tid == 0) st_rel(myflag, t + 1);
    }
}

// ---------------- epilogue: block = (half, 4 rt-cells), thread = vocab scalar ----------------
__global__ __launch_bounds__(256) void out_kernel(
    float* __restrict__ outp, const float* __restrict__ b_out)
{
    __shared__ __align__(16) u64 hp[32][16];   // [k][cp]; cp = rt_i*4 + bpair
    const int tid  = threadIdx.x;
    const int half = blockIdx.x & 1;
    const int rt0  = (blockIdx.x >> 1) * 4;

    {
        int rt_i = tid >> 6, rem = tid & 63;
        float4 hv = __ldcg(&((const float4*)g_hout)[(rt0 + rt_i) * 128 +
                                                    (half * 8 + (rem >> 3)) * 8 + (rem & 7)]);
        int b = rem >> 3, kq = (rem & 7) * 4;
        int cp = rt_i * 4 + (b >> 1), hf = b & 1;
        ((float*)&hp[kq + 0][cp])[hf] = hv.x;
        ((float*)&hp[kq + 1][cp])[hf] = hv.y;
        ((float*)&hp[kq + 2][cp])[hf] = hv.z;
        ((float*)&hp[kq + 3][cp])[hf] = hv.w;
    }
    __syncthreads();

    for (int v = tid; v < NVOCAB; v += 256) {
        u64 acc[16];
        const u64 bia = dup2(__ldg(&b_out[v]));
        #pragma unroll
        for (int cp = 0; cp < 16; ++cp) acc[cp] = bia;
        #pragma unroll
        for (int k = 0; k < 32; ++k) {
            const u64 wv = dup2(__ldg(&g_wvt[k * NVOCAB + v]));
            const ulonglong2* hk = (const ulonglong2*)hp[k];
            #pragma unroll
            for (int qq = 0; qq < 8; ++qq) {
                ulonglong2 h2 = hk[qq];
                acc[2 * qq + 0] = fma2(wv, h2.x, acc[2 * qq + 0]);
                acc[2 * qq + 1] = fma2(wv, h2.y, acc[2 * qq + 1]);
            }
        }
        #pragma unroll
        for (int cp = 0; cp < 16; ++cp) {
            int rt_i = cp >> 2, bpp = cp & 3;
            long rt = rt0 + rt_i;
            long bb0 = half * 8 + 2 * bpp;
            float2 o = unpk(acc[cp]);
            outp[(bb0 * (NROWS * NT) + rt) * NVOCAB + v] = o.x;
            outp[((bb0 + 1) * (NROWS * NT) + rt) * NVOCAB + v] = o.y;
        }
    }
}

// ---------------- launch: positions (1 prep, 2 reset, 3 noop, 4 rnn, 5 out) ----------------
extern "C" void kernel_launch(void* const* d_in, const int* in_sizes, int n_in,
                              void* d_out, int out_size)
{
    (void)in_sizes; (void)n_in; (void)out_size;
    const int*   x     = (const int*)  d_in[0];
    const float* embed = (const float*)d_in[1];
    const float* wih0  = (const float*)d_in[2];
    const float* whh0  = (const float*)d_in[3];
    const float* bih0  = (const float*)d_in[4];
    const float* bhh0  = (const float*)d_in[5];
    const float* wih1  = (const float*)d_in[6];
    const float* whh1  = (const float*)d_in[7];
    const float* bih1  = (const float*)d_in[8];
    const float* bhh1  = (const float*)d_in[9];
    const float* wih2  = (const float*)d_in[10];
    const float* whh2  = (const float*)d_in[11];
    const float* bih2  = (const float*)d_in[12];
    const float* bhh2  = (const float*)d_in[13];
    const float* w_h2e = (const float*)d_in[14];
    const float* b_h2e = (const float*)d_in[15];
    const float* w_out = (const float*)d_in[16];
    const float* b_out = (const float*)d_in[17];
    float* outp = (float*)d_out;

    cudaFuncSetAttribute(rnn_kernel, cudaFuncAttributeMaxDynamicSharedMemorySize, SMEM_RNN);

    prep_kernel<<<260, 96>>>(embed, wih0, whh0, wih1, whh1, wih2, whh2,
                             w_h2e, b_h2e, bih0, w_out);
    reset_kernel<<<1, 256>>>();
    noop_kernel<<<1, 32>>>();
    rnn_kernel<<<NROWS * 2, 128, SMEM_RNN>>>(x, bhh0, bih1, bhh1, bih2, bhh2);
    out_kernel<<<(NROWS * NT / 4) * 2, 256>>>(outp, b_out);
}